// round 3
// baseline (speedup 1.0000x reference)
#include <cuda_runtime.h>

typedef unsigned long long u64;

#define B_    8
#define P_    75
#define HW_   196
#define C_    384
#define H_    6
#define D_    64
#define M_    25
#define SCALE_ 0.125f

#define KSTR  68    // kv row stride (floats): 68%32=4 -> LDS.128 conflict-free (8-lane phases)
#define CSTR  200   // logits row stride
#define ASTR  28    // aT row stride (m padded 25->28, 112B, 16B-aligned)

#define OFF_QS (HW_*KSTR)
#define OFF_C  (OFF_QS + M_*D_)
#define OFF_AT (OFF_C + M_*CSTR)
#define OFF_RS (OFF_AT + HW_*ASTR)
#define SMEM_FLOATS (OFF_RS + 32)
#define SMEM_BYTES  (SMEM_FLOATS * 4)

__device__ __forceinline__ u64 fma2(u64 a, u64 b, u64 c) {
    u64 d; asm("fma.rn.f32x2 %0, %1, %2, %3;" : "=l"(d) : "l"(a), "l"(b), "l"(c)); return d;
}
__device__ __forceinline__ u64 add2(u64 a, u64 b) {
    u64 d; asm("add.rn.f32x2 %0, %1, %2;" : "=l"(d) : "l"(a), "l"(b)); return d;
}
__device__ __forceinline__ u64 splat(float x) {
    u64 d; asm("mov.b64 %0, {%1, %1};" : "=l"(d) : "f"(x)); return d;
}
__device__ __forceinline__ float hsum(u64 v) {
    float lo, hi; asm("mov.b64 {%0, %1}, %2;" : "=f"(lo), "=f"(hi) : "l"(v)); return lo + hi;
}
__device__ __forceinline__ float2 unp(u64 v) {
    float lo, hi; asm("mov.b64 {%0, %1}, %2;" : "=f"(lo), "=f"(hi) : "l"(v)); return make_float2(lo, hi);
}

// QK: c[m][w] = sum_d q[m][d]*kv[w][d], packed over d, horizontal add at end.
// Warp covers MT m-rows x 98 w (its group) via 4 w-slots (lane + 32j; slot 3 = 2 leftover cols).
template<int MT>
__device__ __forceinline__ void qk_loop(const float* __restrict__ kvs,
                                        const float* __restrict__ qss,
                                        float* __restrict__ cbuf,
                                        int mbase, int wbase, int lane)
{
    u64 acc[MT][4];
    #pragma unroll
    for (int mi = 0; mi < MT; mi++) { acc[mi][0] = 0; acc[mi][1] = 0; acc[mi][2] = 0; acc[mi][3] = 0; }

    const int wj0 = wbase + lane;
    const int wj1 = wbase + 32 + lane;
    const int wj2 = wbase + 64 + lane;
    const int wj3 = wbase + 96 + (lane & 1);   // all lanes load valid addr; only lanes 0,1 write

    #pragma unroll 2
    for (int d4 = 0; d4 < 16; d4++) {
        ulonglong2 q[MT];
        #pragma unroll
        for (int mi = 0; mi < MT; mi++)
            q[mi] = *(const ulonglong2*)&qss[(mbase + mi) * D_ + d4 * 4];
        const int wj[4] = {wj0, wj1, wj2, wj3};
        #pragma unroll
        for (int j = 0; j < 4; j++) {
            ulonglong2 k = *(const ulonglong2*)&kvs[wj[j] * KSTR + d4 * 4];
            #pragma unroll
            for (int mi = 0; mi < MT; mi++) {
                acc[mi][j] = fma2(q[mi].x, k.x, acc[mi][j]);
                acc[mi][j] = fma2(q[mi].y, k.y, acc[mi][j]);
            }
        }
    }
    #pragma unroll
    for (int mi = 0; mi < MT; mi++) {
        cbuf[(mbase + mi) * CSTR + wj0] = hsum(acc[mi][0]);
        cbuf[(mbase + mi) * CSTR + wj1] = hsum(acc[mi][1]);
        cbuf[(mbase + mi) * CSTR + wj2] = hsum(acc[mi][2]);
    }
    if (lane < 2) {
        #pragma unroll
        for (int mi = 0; mi < MT; mi++)
            cbuf[(mbase + mi) * CSTR + wj3] = hsum(acc[mi][3]);
    }
}

__global__ void __launch_bounds__(256, 2)
tokenqkv_attn_kernel(const float* __restrict__ xq_g,
                     const float* __restrict__ xs_g,
                     float* __restrict__ out)
{
    extern __shared__ float sm[];
    float* kvs  = sm;                // 196 x 68
    float* qss  = sm + OFF_QS;       // 25 x 64
    float* cbuf = sm + OFF_C;        // 25 x 200 logits
    float* aT   = sm + OFF_AT;       // 196 x 28 (exp, transposed)
    float* rs   = sm + OFF_RS;       // 25 row 1/sum

    const int tid = threadIdx.x, lane = tid & 31, wid = tid >> 5;
    const int h = blockIdx.x, p = blockIdx.y, b = blockIdx.z;

    const float* xq  = xq_g + ((size_t)(b * P_ + p)) * HW_ * C_ + h * D_;
    const float* xsh = xs_g + (size_t)b * M_ * C_ + h * D_;

    // ---- stage kv (196x64) and qs (25x64) ----
    for (int i = tid; i < HW_ * 16; i += 256) {
        int w = i >> 4, c = (i & 15) << 2;
        *(float4*)&kvs[w * KSTR + c] = *(const float4*)(xq + (size_t)w * C_ + c);
    }
    for (int i = tid; i < M_ * 16; i += 256) {
        int m = i >> 4, c = (i & 15) << 2;
        *(float4*)&qss[m * D_ + c] = *(const float4*)(xsh + (size_t)m * C_ + c);
    }
    // ---- fold o_support copy into the 8 (h==0,p==0) blocks ----
    if (h == 0 && p == 0) {
        const float4* src = (const float4*)(xs_g + (size_t)b * M_ * C_);
        float4* dst = (float4*)(out + (size_t)B_ * P_ * M_ * C_ + (size_t)b * M_ * C_);
        for (int i = tid; i < M_ * C_ / 4; i += 256) dst[i] = src[i];
    }
    __syncthreads();

    // ---- QK: 2 w-groups x 4 m-warps (7,6,6,6) ----
    {
        const int grp = wid >> 2, mw = wid & 3;
        const int wbase = grp * 98;
        if      (mw == 0) qk_loop<7>(kvs, qss, cbuf, 0,  wbase, lane);
        else if (mw == 1) qk_loop<6>(kvs, qss, cbuf, 7,  wbase, lane);
        else if (mw == 2) qk_loop<6>(kvs, qss, cbuf, 13, wbase, lane);
        else              qk_loop<6>(kvs, qss, cbuf, 19, wbase, lane);
    }
    __syncthreads();

    // ---- softmax per m-row; write exp transposed into aT[w][m] ----
    for (int r = wid; r < M_; r += 8) {
        const float* crow = cbuf + r * CSTR;
        float vmax = -1e30f;
        for (int k = lane; k < HW_; k += 32) vmax = fmaxf(vmax, crow[k]);
        #pragma unroll
        for (int o = 16; o; o >>= 1) vmax = fmaxf(vmax, __shfl_xor_sync(0xffffffffu, vmax, o));
        float s = 0.0f;
        for (int k = lane; k < HW_; k += 32) {
            float e = __expf((crow[k] - vmax) * SCALE_);
            aT[k * ASTR + r] = e;
            s += e;
        }
        #pragma unroll
        for (int o = 16; o; o >>= 1) s += __shfl_xor_sync(0xffffffffu, s, o);
        if (lane == 0) rs[r] = 1.0f / s;
    }
    __syncthreads();

    // ---- AV: warps split w (warps 0-3: 25 w, warps 4-7: 24 w); lane = d-pair ----
    // Software-pipelined: double-buffered aT row + kv chunk prefetch.
    u64 acc[M_];
    #pragma unroll
    for (int m = 0; m < M_; m++) acc[m] = 0;
    {
        const int nw = (wid < 4) ? 25 : 24;
        const int ws = (wid < 4) ? wid * 25 : 100 + (wid - 4) * 24;

        float ab[2][28];
        u64 kb[2];

        #define AV_LOAD(BUF, W) do {                                          \
            const float* _ar = &aT[(W) * ASTR];                               \
            _Pragma("unroll")                                                 \
            for (int g = 0; g < 7; g++)                                       \
                *(float4*)&ab[BUF][g * 4] = *(const float4*)&_ar[g * 4];      \
            kb[BUF] = *(const u64*)&kvs[(W) * KSTR + 2 * lane];               \
        } while (0)

        #define AV_FMA(BUF) do {                                              \
            _Pragma("unroll")                                                 \
            for (int m = 0; m < M_; m++)                                      \
                acc[m] = fma2(splat(ab[BUF][m]), kb[BUF], acc[m]);            \
        } while (0)

        AV_LOAD(0, ws);
        int i = 0;
        for (; i + 2 <= nw - 1; i += 2) {
            AV_LOAD(1, ws + i + 1);
            AV_FMA(0);
            AV_LOAD(0, ws + i + 2);
            AV_FMA(1);
        }
        if (i < nw - 1) {           // one prefetched pair left
            AV_LOAD(1, ws + i + 1);
            AV_FMA(0);
            AV_FMA(1);
        } else {
            AV_FMA(0);
        }
        #undef AV_LOAD
        #undef AV_FMA
    }
    __syncthreads();   // everyone done reading kv/aT -> safe to alias kv with partials

    // ---- cross-warp reduction via smem partials (aliased into kv region) ----
    u64* part = (u64*)sm;   // 8 x 800 u64 = 51.2KB <= kv region 53.3KB
    #pragma unroll
    for (int m = 0; m < M_; m++)
        part[wid * 800 + m * 32 + lane] = acc[m];
    __syncthreads();

    float* outb = out + ((size_t)(b * P_ + p) * M_) * C_ + h * D_;
    #pragma unroll 1
    for (int base = tid; base < 800; base += 256) {
        u64 s = part[base];
        #pragma unroll
        for (int k2 = 1; k2 < 8; k2++) s = add2(s, part[k2 * 800 + base]);
        int m = base >> 5, dp = base & 31;
        float sc = rs[m];
        float2 v = unp(s);
        v.x *= sc; v.y *= sc;
        *(float2*)&outb[(size_t)m * C_ + 2 * dp] = v;
    }
}

extern "C" void kernel_launch(void* const* d_in, const int* in_sizes, int n_in,
                              void* d_out, int out_size) {
    const float* xq = (const float*)d_in[0];   // (8,5,15,196,384)
    const float* xs = (const float*)d_in[1];   // (8,25,384)
    float* out = (float*)d_out;

    cudaFuncSetAttribute(tokenqkv_attn_kernel,
                         cudaFuncAttributeMaxDynamicSharedMemorySize, SMEM_BYTES);

    dim3 grid(H_, P_, B_);
    tokenqkv_attn_kernel<<<grid, 256, SMEM_BYTES>>>(xq, xs, out);
}